// round 1
// baseline (speedup 1.0000x reference)
#include <cuda_runtime.h>
#include <float.h>
#include <math.h>

#define BB 32
#define NN 24564
#define NC 21
#define TOPKK 200
#define NMSOUT 50
#define CONF_T 0.5f
#define IOU_T 0.45f
#define CAP 1024
#define ROWS_PER_B (NC * NMSOUT) /* 1050 */

// Scratch (static device globals; no runtime allocation)
__device__ float  g_scores[(size_t)BB * NC * NN];   // transposed conf (B, C, N)
__device__ float4 g_boxes[(size_t)BB * NN];          // decoded boxes
__device__ float  g_rows[(size_t)BB * ROWS_PER_B * 6];

// ---------------------------------------------------------------------------
// Kernel 1: decode boxes + transpose conf to (B, C, N)
// ---------------------------------------------------------------------------
__global__ __launch_bounds__(256) void k_decode(const float* __restrict__ pred) {
    __shared__ float stage[8][33 * 32];
    const int b = blockIdx.y;
    const int w = threadIdx.x >> 5, lane = threadIdx.x & 31;
    const int a0 = blockIdx.x * 256 + w * 32;

    const float* P = pred + (size_t)b * NN * 33;
    const long base = (long)a0 * 33;
#pragma unroll
    for (int k = 0; k < 33; k++) {
        long e = base + k * 32 + lane;
        stage[w][k * 32 + lane] = (e < (long)NN * 33) ? P[e] : 0.0f;
    }
    __syncwarp();

    const int a = a0 + lane;
    if (a < NN) {
        const float* r = &stage[w][lane * 33];
        float l0 = r[21], l1 = r[22], l2 = r[23], l3 = r[24];
        float ax = r[25], ay = r[26], aw = r[27], ah = r[28];
        float v0 = r[29], v1 = r[30], v2 = r[31], v3 = r[32];
        float cx = l0 * aw * v0 + ax;
        float cy = l1 * ah * v1 + ay;
        float wb = expf(l2 * v2) * aw;
        float hb = expf(l3 * v3) * ah;
        float xmin = (cx - 0.5f * wb) * 512.0f;
        float xmax = (cx + 0.5f * wb) * 512.0f;
        float ymin = (cy - 0.5f * hb) * 512.0f;
        float ymax = (cy + 0.5f * hb) * 512.0f;
        g_boxes[(size_t)b * NN + a] = make_float4(xmin, ymin, xmax, ymax);
#pragma unroll
        for (int c = 0; c < NC; c++)
            g_scores[((size_t)b * NC + c) * NN + a] = r[c];
    }
}

// ---------------------------------------------------------------------------
// Kernel 2: per (b, c): exact top-200 (value desc, idx asc) + 50-step NMS
// ---------------------------------------------------------------------------
__global__ __launch_bounds__(256) void k_nms() {
    const int bc = blockIdx.x;
    const int b = bc / NC, c = bc % NC;
    const float* __restrict__ S = g_scores + ((size_t)b * NC + c) * NN;
    const int tid = threadIdx.x;

    __shared__ unsigned hist[256];
    __shared__ unsigned suf[257];
    __shared__ int s_bin, s_K, s_under;
    __shared__ unsigned s_cnt;
    __shared__ float cs[CAP];
    __shared__ int   ci[CAP];
    __shared__ float nsc[TOPKK];
    __shared__ float tsc[TOPKK];
    __shared__ float4 cbox[TOPKK];
    __shared__ int sel[NMSOUT];
    __shared__ unsigned char valf[NMSOUT];
    __shared__ float wv[8];
    __shared__ int   wi[8];
    __shared__ float s_bv;
    __shared__ int   s_bi;

    // ---- Phase A: find the bit pattern of the 200th-largest masked score ----
    // scores in (0.5, 1.0): bits - 0x3F000000 spans (0, 2^23]. Three histogram
    // refinement passes: 8 bits, 8 bits, 7 bits.
    int K = TOPKK;
    unsigned prefix = 0;
    bool under = false;
    unsigned offstar = 1u;

    for (int pass = 0; pass < 3; pass++) {
        const int nb = (pass == 2) ? 128 : 256;
        for (int i = tid; i < 256; i += 256) hist[i] = 0u;
        __syncthreads();
        for (int n = tid; n < NN; n += 256) {
            float s = S[n];
            if (s > CONF_T) {
                unsigned off = __float_as_uint(s) - 0x3F000000u;
                if (off > 0x7FFFFFu) off = 0x7FFFFFu;
                if (pass == 0) {
                    atomicAdd(&hist[off >> 15], 1u);
                } else if (pass == 1) {
                    if ((off >> 15) == prefix) atomicAdd(&hist[(off >> 7) & 0xFFu], 1u);
                } else {
                    if ((off >> 7) == prefix) atomicAdd(&hist[off & 0x7Fu], 1u);
                }
            }
        }
        __syncthreads();
        // suffix sums: suf[i] = sum_{j>=i} hist[j]
        if (tid <= nb) {
            unsigned sum = 0;
            for (int j = tid; j < nb; j++) sum += hist[j];
            suf[tid] = sum;
        }
        __syncthreads();
        if (pass == 0) {
            if (tid == 0) s_under = (suf[0] < (unsigned)K) ? 1 : 0;
            __syncthreads();
            if (s_under) { under = true; break; }  // fewer than 200 candidates
        }
        if (tid < nb) {
            if (suf[tid] >= (unsigned)K && suf[tid + 1] < (unsigned)K) {
                s_bin = tid;
                s_K = K - (int)suf[tid + 1];
            }
        }
        __syncthreads();
        if (pass == 0)      prefix = (unsigned)s_bin;
        else if (pass == 1) prefix = (prefix << 8) | (unsigned)s_bin;
        else                offstar = (prefix << 7) | (unsigned)s_bin;
        K = s_K;
        __syncthreads();
    }
    if (under) offstar = 1u;  // collect everything > CONF_T

    // ---- Phase B: compact all entries with score-bits >= offstar ----
    if (tid == 0) s_cnt = 0u;
    __syncthreads();
    for (int n = tid; n < NN; n += 256) {
        float s = S[n];
        if (s > CONF_T) {
            unsigned off = __float_as_uint(s) - 0x3F000000u;
            if (off > 0x7FFFFFu) off = 0x7FFFFFu;
            if (off >= offstar) {
                unsigned p = atomicAdd(&s_cnt, 1u);
                if (p < CAP) { cs[p] = s; ci[p] = n; }
            }
        }
    }
    __syncthreads();
    const unsigned cnt = (s_cnt < CAP) ? s_cnt : CAP;
    for (int i = tid; i < CAP; i += 256) {
        if ((unsigned)i >= cnt) { cs[i] = -FLT_MAX; ci[i] = 0x7FFFFFFF; }
    }
    __syncthreads();

    // ---- Phase C: bitonic sort (score desc, idx asc) over CAP entries ----
    for (int k = 2; k <= CAP; k <<= 1) {
        for (int j = k >> 1; j > 0; j >>= 1) {
            for (int i = tid; i < CAP; i += 256) {
                int x = i ^ j;
                if (x > i) {
                    float a = cs[i], d = cs[x];
                    int ia = ci[i], ib = ci[x];
                    bool a_first = (a > d) || (a == d && ia < ib);
                    bool up = ((i & k) == 0);
                    if (up != a_first) {
                        cs[i] = d; ci[i] = ib;
                        cs[x] = a; ci[x] = ia;
                    }
                }
            }
            __syncthreads();
        }
    }

    // ---- Phase D: load top-200 candidate boxes ----
    if (tid < TOPKK) {
        float s = cs[tid];
        nsc[tid] = s;
        tsc[tid] = s;
        int id = ci[tid];
        cbox[tid] = (id >= 0 && id < NN) ? g_boxes[(size_t)b * NN + id]
                                         : make_float4(0.f, 0.f, 0.f, 0.f);
    }
    __syncthreads();

    // ---- Phase E: sequential NMS, 50 steps ----
    for (int kk = 0; kk < NMSOUT; kk++) {
        // block argmax: (score desc, position asc)
        float v = (tid < TOPKK) ? nsc[tid] : -FLT_MAX;
        int bi = tid;
#pragma unroll
        for (int o = 16; o > 0; o >>= 1) {
            float ov = __shfl_down_sync(0xFFFFFFFFu, v, o);
            int oi = __shfl_down_sync(0xFFFFFFFFu, bi, o);
            if (ov > v || (ov == v && oi < bi)) { v = ov; bi = oi; }
        }
        if ((tid & 31) == 0) { wv[tid >> 5] = v; wi[tid >> 5] = bi; }
        __syncthreads();
        if (tid < 32) {
            float v2 = (tid < 8) ? wv[tid] : -FLT_MAX;
            int b2 = (tid < 8) ? wi[tid] : 0x7FFFFFFF;
#pragma unroll
            for (int o = 4; o > 0; o >>= 1) {
                float ov = __shfl_down_sync(0xFFFFFFFFu, v2, o);
                int oi = __shfl_down_sync(0xFFFFFFFFu, b2, o);
                if (ov > v2 || (ov == v2 && oi < b2)) { v2 = ov; b2 = oi; }
            }
            if (tid == 0) { s_bv = v2; s_bi = b2; }
        }
        __syncthreads();

        const int i = s_bi;
        const bool valid = (s_bv > 0.0f);
        if (valid && tid < TOPKK) {
            float4 bbx = cbox[i];
            float4 cb = cbox[tid];
            float x1 = fmaxf(bbx.x, cb.x);
            float y1 = fmaxf(bbx.y, cb.y);
            float x2 = fminf(bbx.z, cb.z);
            float y2 = fminf(bbx.w, cb.w);
            float inter = fmaxf(x2 - x1, 0.0f) * fmaxf(y2 - y1, 0.0f);
            float ab = (bbx.z - bbx.x) * (bbx.w - bbx.y);
            float ac = (cb.z - cb.x) * (cb.w - cb.y);
            float iou = inter / (ab + ac - inter + 1e-8f);
            if (iou > IOU_T || tid == i) nsc[tid] = -1.0f;
        }
        if (tid == 0) { sel[kk] = i; valf[kk] = valid ? 1 : 0; }
        __syncthreads();
    }

    // ---- Phase F: write 50 rows ----
    for (int e = tid; e < NMSOUT * 6; e += 256) {
        int r = e / 6, col = e % 6;
        float vout = 0.0f;
        if (valf[r]) {
            int i = sel[r];
            if (col == 0)      vout = (float)c;
            else if (col == 1) vout = tsc[i];
            else {
                float4 bx = cbox[i];
                vout = (col == 2) ? bx.x : (col == 3) ? bx.y : (col == 4) ? bx.z : bx.w;
            }
        }
        g_rows[((size_t)b * ROWS_PER_B + c * NMSOUT + r) * 6 + col] = vout;
    }
}

// ---------------------------------------------------------------------------
// Kernel 3: per-batch top-200 of the 1050 rows (score desc, idx asc)
// ---------------------------------------------------------------------------
__global__ __launch_bounds__(256) void k_final(float* __restrict__ out) {
    __shared__ float ks[2048];
    __shared__ int   kid[2048];
    const int b = blockIdx.x;
    const int tid = threadIdx.x;

    for (int i = tid; i < 2048; i += 256) {
        if (i < ROWS_PER_B) {
            ks[i] = g_rows[((size_t)b * ROWS_PER_B + i) * 6 + 1];
            kid[i] = i;
        } else {
            ks[i] = -FLT_MAX;
            kid[i] = 0x7FFFFFFF;
        }
    }
    __syncthreads();

    for (int k = 2; k <= 2048; k <<= 1) {
        for (int j = k >> 1; j > 0; j >>= 1) {
            for (int i = tid; i < 2048; i += 256) {
                int x = i ^ j;
                if (x > i) {
                    float a = ks[i], d = ks[x];
                    int ia = kid[i], ib = kid[x];
                    bool a_first = (a > d) || (a == d && ia < ib);
                    bool up = ((i & k) == 0);
                    if (up != a_first) {
                        ks[i] = d; kid[i] = ib;
                        ks[x] = a; kid[x] = ia;
                    }
                }
            }
            __syncthreads();
        }
    }

    for (int e = tid; e < TOPKK * 6; e += 256) {
        int r = e / 6, col = e % 6;
        out[(size_t)b * TOPKK * 6 + e] =
            g_rows[((size_t)b * ROWS_PER_B + kid[r]) * 6 + col];
    }
}

extern "C" void kernel_launch(void* const* d_in, const int* in_sizes, int n_in,
                              void* d_out, int out_size) {
    const float* pred = (const float*)d_in[0];
    float* out = (float*)d_out;
    dim3 g1((NN + 255) / 256, BB);
    k_decode<<<g1, 256>>>(pred);
    k_nms<<<BB * NC, 256>>>();
    k_final<<<BB, 256>>>(out);
}